// round 1
// baseline (speedup 1.0000x reference)
#include <cuda_runtime.h>
#include <cuda_bf16.h>
#include <math_constants.h>

#define NN_NODES 20000
#define EE_EDGES 320000
#define FF 128
#define HH1 3

// ---------------- scratch (static device allocations; no cudaMalloc) ----------------
__device__ float g_h1[NN_NODES * HH1 * FF];    // layer1 projected features [N,3,128]
__device__ float g_rst1[NN_NODES * HH1 * FF];  // layer1 output [N,384]
__device__ float g_h2[NN_NODES * FF];          // layer2 projected features [N,128]
__device__ float g_el1[NN_NODES * HH1];
__device__ float g_er1[NN_NODES * HH1];
__device__ float g_el2[NN_NODES];
__device__ float g_er2[NN_NODES];
__device__ int   g_row[NN_NODES + 1];          // CSR row offsets by dst
__device__ int   g_cursor[NN_NODES];
__device__ int   g_srcp[EE_EDGES];             // src node per CSR slot
__device__ int   g_bsums[64];

// ---------------- CSR build ----------------
__global__ void zero_counts_k(int* row) {
    int i = blockIdx.x * blockDim.x + threadIdx.x;
    if (i <= NN_NODES) row[i] = 0;
}

__global__ void count_k(const int* __restrict__ dst, int* row) {
    int e = blockIdx.x * blockDim.x + threadIdx.x;
    if (e < EE_EDGES) atomicAdd(&row[dst[e]], 1);
}

__global__ void scan_block_k(int* __restrict__ row, int* __restrict__ bsums, int n) {
    __shared__ int sm[512];
    int i = blockIdx.x * 512 + threadIdx.x;
    int v = (i < n) ? row[i] : 0;
    sm[threadIdx.x] = v;
    __syncthreads();
    #pragma unroll
    for (int off = 1; off < 512; off <<= 1) {
        int t = (threadIdx.x >= off) ? sm[threadIdx.x - off] : 0;
        __syncthreads();
        sm[threadIdx.x] += t;
        __syncthreads();
    }
    int incl = sm[threadIdx.x];
    if (i < n) row[i] = incl - v;  // exclusive within block
    if (threadIdx.x == 511) bsums[blockIdx.x] = incl;
}

__global__ void scan_sums_k(int* bsums, int nb) {
    if (threadIdx.x == 0 && blockIdx.x == 0) {
        int acc = 0;
        for (int i = 0; i < nb; i++) { int t = bsums[i]; bsums[i] = acc; acc += t; }
    }
}

__global__ void scan_add_k(int* __restrict__ row, const int* __restrict__ bsums,
                           int* __restrict__ cursor, int n) {
    int i = blockIdx.x * blockDim.x + threadIdx.x;
    if (i < n) {
        int v = row[i] + bsums[i >> 9];
        row[i] = v;
        cursor[i] = v;
    }
    if (i == 0) row[n] = EE_EDGES;
}

__global__ void scatter_k(const int* __restrict__ src, const int* __restrict__ dst,
                          int* cursor, int* __restrict__ srcp) {
    int e = blockIdx.x * blockDim.x + threadIdx.x;
    if (e < EE_EDGES) {
        int p = atomicAdd(&cursor[dst[e]], 1);
        srcp[p] = src[e];
    }
}

// ---------------- fp32 SIMT GEMM: C[M,NN] = A[M,K] @ B[K,NN] ----------------
// BM=BN=128, BK=8, 256 threads, 8x8 per thread. K, NN multiples of 8/128.
__global__ __launch_bounds__(256) void sgemm128(const float* __restrict__ A,
                                                const float* __restrict__ B,
                                                float* __restrict__ C,
                                                int M, int K, int NCOLS) {
    __shared__ float As[8][128];
    __shared__ float Bs[8][128];
    int bm = blockIdx.x, bn = blockIdx.y;
    int t = threadIdx.x;
    int tx = t & 15, ty = t >> 4;
    float acc[8][8];
    #pragma unroll
    for (int i = 0; i < 8; i++)
        #pragma unroll
        for (int j = 0; j < 8; j++) acc[i][j] = 0.f;

    int aRow = t >> 1, aCol = (t & 1) * 4;
    int bRow = t >> 5, bCol = (t & 31) * 4;
    int gRow = bm * 128 + aRow;
    bool aValid = gRow < M;
    const float* Ab = A + (size_t)(aValid ? gRow : 0) * K + aCol;
    const float* Bb = B + (size_t)bRow * NCOLS + bn * 128 + bCol;

    for (int k0 = 0; k0 < K; k0 += 8) {
        float4 av = aValid ? *(const float4*)(Ab + k0) : make_float4(0.f, 0.f, 0.f, 0.f);
        float4 bv = *(const float4*)(Bb + (size_t)k0 * NCOLS);
        As[aCol + 0][aRow] = av.x;
        As[aCol + 1][aRow] = av.y;
        As[aCol + 2][aRow] = av.z;
        As[aCol + 3][aRow] = av.w;
        *(float4*)&Bs[bRow][bCol] = bv;
        __syncthreads();
        #pragma unroll
        for (int kk = 0; kk < 8; ++kk) {
            float ra[8], rb[8];
            #pragma unroll
            for (int i = 0; i < 8; i++) ra[i] = As[kk][ty * 8 + i];
            #pragma unroll
            for (int j = 0; j < 8; j++) rb[j] = Bs[kk][tx * 8 + j];
            #pragma unroll
            for (int i = 0; i < 8; i++)
                #pragma unroll
                for (int j = 0; j < 8; j++) acc[i][j] += ra[i] * rb[j];
        }
        __syncthreads();
    }
    #pragma unroll
    for (int i = 0; i < 8; i++) {
        int row = bm * 128 + ty * 8 + i;
        if (row < M) {
            float* Cp = C + (size_t)row * NCOLS + bn * 128 + tx * 8;
            *(float4*)Cp = make_float4(acc[i][0], acc[i][1], acc[i][2], acc[i][3]);
            *(float4*)(Cp + 4) = make_float4(acc[i][4], acc[i][5], acc[i][6], acc[i][7]);
        }
    }
}

// ---------------- per-(node,head) attention scores el/er ----------------
// one warp per (node*heads + head); h layout [n][heads][128]
__global__ void score_k(const float* __restrict__ h, const float* __restrict__ al,
                        const float* __restrict__ ar, float* __restrict__ el,
                        float* __restrict__ er, int heads) {
    int g = blockIdx.x * blockDim.x + threadIdx.x;
    int w = g >> 5, lane = g & 31;
    if (w >= NN_NODES * heads) return;
    int hh = w % heads;
    float4 x = ((const float4*)(h + (size_t)w * 128))[lane];
    float4 a = ((const float4*)(al + hh * 128))[lane];
    float4 b = ((const float4*)(ar + hh * 128))[lane];
    float sl = x.x * a.x + x.y * a.y + x.z * a.z + x.w * a.w;
    float sr = x.x * b.x + x.y * b.y + x.z * b.z + x.w * b.w;
    #pragma unroll
    for (int o = 16; o; o >>= 1) {
        sl += __shfl_xor_sync(0xffffffffu, sl, o);
        sr += __shfl_xor_sync(0xffffffffu, sr, o);
    }
    if (lane == 0) { el[w] = sl; er[w] = sr; }
}

// ---------------- edge-softmax aggregation: one warp per dst node ----------------
template <int HEADS>
__global__ void agg_kernel(const float* __restrict__ hfeat,   // [N, HEADS*128]
                           const float* __restrict__ el,      // [N*HEADS]
                           const float* __restrict__ er,      // [N*HEADS]
                           const float* __restrict__ bias,    // [HEADS*128]
                           const int* __restrict__ row,
                           const int* __restrict__ srcp,
                           float* __restrict__ out) {         // [N, HEADS*128]
    int w = (blockIdx.x * blockDim.x + threadIdx.x) >> 5;
    int lane = threadIdx.x & 31;
    if (w >= NN_NODES) return;
    int d = w;
    int s0 = row[d], s1 = row[d + 1];

    float erd[HEADS];
    #pragma unroll
    for (int h = 0; h < HEADS; h++) erd[h] = er[d * HEADS + h];

    // pass 1: per-head max of leaky_relu(el[src]+er[dst]) over incoming edges
    float m[HEADS];
    #pragma unroll
    for (int h = 0; h < HEADS; h++) m[h] = -CUDART_INF_F;
    for (int i = s0 + lane; i < s1; i += 32) {
        int s = srcp[i];
        #pragma unroll
        for (int h = 0; h < HEADS; h++) {
            float e = el[s * HEADS + h] + erd[h];
            e = (e > 0.f) ? e : 0.2f * e;
            m[h] = fmaxf(m[h], e);
        }
    }
    #pragma unroll
    for (int h = 0; h < HEADS; h++)
        #pragma unroll
        for (int o = 16; o; o >>= 1)
            m[h] = fmaxf(m[h], __shfl_xor_sync(0xffffffffu, m[h], o));

    // pass 2: accumulate exp-weights and weighted feature sums
    float4 acc[HEADS];
    float den[HEADS];
    #pragma unroll
    for (int h = 0; h < HEADS; h++) {
        acc[h] = make_float4(0.f, 0.f, 0.f, 0.f);
        den[h] = 0.f;
    }
    for (int i = s0; i < s1; ++i) {
        int s = srcp[i];  // broadcast load (same address all lanes)
        #pragma unroll
        for (int h = 0; h < HEADS; h++) {
            float e = el[s * HEADS + h] + erd[h];
            e = (e > 0.f) ? e : 0.2f * e;
            float wg = __expf(e - m[h]);
            den[h] += wg;
            float4 v = *(const float4*)(hfeat + (size_t)s * (HEADS * 128) + h * 128 + lane * 4);
            acc[h].x += wg * v.x;
            acc[h].y += wg * v.y;
            acc[h].z += wg * v.z;
            acc[h].w += wg * v.w;
        }
    }
    #pragma unroll
    for (int h = 0; h < HEADS; h++) {
        float inv = 1.0f / den[h];
        float4 b4 = *(const float4*)(bias + h * 128 + lane * 4);
        float4 r;
        r.x = acc[h].x * inv + b4.x;
        r.y = acc[h].y * inv + b4.y;
        r.z = acc[h].z * inv + b4.z;
        r.w = acc[h].w * inv + b4.w;
        *(float4*)(out + (size_t)d * (HEADS * 128) + h * 128 + lane * 4) = r;
    }
}

// ---------------- launch ----------------
static inline int cdiv(int a, int b) { return (a + b - 1) / b; }

extern "C" void kernel_launch(void* const* d_in, const int* in_sizes, int n_in,
                              void* d_out, int out_size) {
    const float* feats   = (const float*)d_in[0];   // [20000,128]
    const float* W1      = (const float*)d_in[1];   // [128,384]
    const float* attn_l1 = (const float*)d_in[2];   // [3,128]
    const float* attn_r1 = (const float*)d_in[3];   // [3,128]
    const float* bias1   = (const float*)d_in[4];   // [384]
    const float* W2      = (const float*)d_in[5];   // [384,128]
    const float* attn_l2 = (const float*)d_in[6];   // [1,128]
    const float* attn_r2 = (const float*)d_in[7];   // [1,128]
    const float* bias2   = (const float*)d_in[8];   // [128]
    const int*   src     = (const int*)d_in[9];     // [320000]
    const int*   dst     = (const int*)d_in[10];    // [320000]
    float* out = (float*)d_out;                     // [20000,128]

    float *h1, *rst1, *h2, *el1, *er1, *el2, *er2;
    int *row, *cursor, *srcp, *bsums;
    cudaGetSymbolAddress((void**)&h1, g_h1);
    cudaGetSymbolAddress((void**)&rst1, g_rst1);
    cudaGetSymbolAddress((void**)&h2, g_h2);
    cudaGetSymbolAddress((void**)&el1, g_el1);
    cudaGetSymbolAddress((void**)&er1, g_er1);
    cudaGetSymbolAddress((void**)&el2, g_el2);
    cudaGetSymbolAddress((void**)&er2, g_er2);
    cudaGetSymbolAddress((void**)&row, g_row);
    cudaGetSymbolAddress((void**)&cursor, g_cursor);
    cudaGetSymbolAddress((void**)&srcp, g_srcp);
    cudaGetSymbolAddress((void**)&bsums, g_bsums);

    const int nb = cdiv(NN_NODES, 512);  // 40 scan blocks

    // CSR build (per-launch; deterministic workload)
    zero_counts_k<<<cdiv(NN_NODES + 1, 256), 256>>>(row);
    count_k<<<cdiv(EE_EDGES, 256), 256>>>(dst, row);
    scan_block_k<<<nb, 512>>>(row, bsums, NN_NODES);
    scan_sums_k<<<1, 32>>>(bsums, nb);
    scan_add_k<<<cdiv(NN_NODES, 256), 256>>>(row, bsums, cursor, NN_NODES);
    scatter_k<<<cdiv(EE_EDGES, 256), 256>>>(src, dst, cursor, srcp);

    // layer 1
    {
        dim3 grid(cdiv(NN_NODES, 128), 3);
        sgemm128<<<grid, 256>>>(feats, W1, h1, NN_NODES, 128, 384);
    }
    score_k<<<cdiv(NN_NODES * HH1 * 32, 256), 256>>>(h1, attn_l1, attn_r1, el1, er1, HH1);
    agg_kernel<HH1><<<cdiv(NN_NODES * 32, 256), 256>>>(h1, el1, er1, bias1, row, srcp, rst1);

    // layer 2
    {
        dim3 grid(cdiv(NN_NODES, 128), 1);
        sgemm128<<<grid, 256>>>(rst1, W2, h2, NN_NODES, 384, 128);
    }
    score_k<<<cdiv(NN_NODES * 32, 256), 256>>>(h2, attn_l2, attn_r2, el2, er2, 1);
    agg_kernel<1><<<cdiv(NN_NODES * 32, 256), 256>>>(h2, el2, er2, bias2, row, srcp, out);
}

// round 2
// speedup vs baseline: 1.0722x; 1.0722x over previous
#include <cuda_runtime.h>
#include <cuda_bf16.h>
#include <math_constants.h>

#define NN_NODES 20000
#define EE_EDGES 320000
#define FF 128
#define HH1 3

// ---------------- scratch (static device allocations; no cudaMalloc) ----------------
__device__ float g_h1[NN_NODES * HH1 * FF];    // layer1 projected features [N,3,128]
__device__ float g_rst1[NN_NODES * HH1 * FF];  // layer1 output [N,384]
__device__ float g_h2[NN_NODES * FF];          // layer2 projected features [N,128]
__device__ float g_el1[NN_NODES * HH1];
__device__ float g_er1[NN_NODES * HH1];
__device__ float g_el2[NN_NODES];
__device__ float g_er2[NN_NODES];
__device__ int   g_row[NN_NODES + 1];          // CSR row offsets by dst
__device__ int   g_cursor[NN_NODES];
__device__ int   g_srcp[EE_EDGES];             // src node per CSR slot
__device__ int   g_bsums[64];

// ---------------- CSR build ----------------
__global__ void zero_counts_k(int* row) {
    int i = blockIdx.x * blockDim.x + threadIdx.x;
    if (i <= NN_NODES) row[i] = 0;
}

__global__ void count_k(const int* __restrict__ dst, int* row) {
    int e = blockIdx.x * blockDim.x + threadIdx.x;
    if (e < EE_EDGES) atomicAdd(&row[dst[e]], 1);
}

__global__ void scan_block_k(int* __restrict__ row, int* __restrict__ bsums, int n) {
    __shared__ int sm[512];
    int i = blockIdx.x * 512 + threadIdx.x;
    int v = (i < n) ? row[i] : 0;
    sm[threadIdx.x] = v;
    __syncthreads();
    #pragma unroll
    for (int off = 1; off < 512; off <<= 1) {
        int t = (threadIdx.x >= off) ? sm[threadIdx.x - off] : 0;
        __syncthreads();
        sm[threadIdx.x] += t;
        __syncthreads();
    }
    int incl = sm[threadIdx.x];
    if (i < n) row[i] = incl - v;  // exclusive within block
    if (threadIdx.x == 511) bsums[blockIdx.x] = incl;
}

// Fused: every block redundantly prefix-scans the (<=64) block sums in-SM,
// then adds the right offset. Removes the serial scan_sums_k kernel.
__global__ void scan_add_k(int* __restrict__ row, const int* __restrict__ bsums,
                           int* __restrict__ cursor, int n, int nb) {
    __shared__ int sb[65];  // sb[b] = exclusive prefix of block b
    int tid = threadIdx.x;
    if (tid == 0) sb[0] = 0;
    if (tid < 64) {
        int v = (tid < nb) ? bsums[tid] : 0;
        int lane = tid & 31;
        #pragma unroll
        for (int o = 1; o < 32; o <<= 1) {
            int t = __shfl_up_sync(0xffffffffu, v, o);
            if (lane >= o) v += t;
        }
        sb[tid + 1] = v;  // inclusive within each warp of 32
    }
    __syncthreads();
    if (tid >= 32 && tid < 64) sb[tid + 1] += sb[32];
    __syncthreads();
    int i = blockIdx.x * blockDim.x + tid;
    if (i < n) {
        int v = row[i] + sb[i >> 9];
        row[i] = v;
        cursor[i] = v;
    }
    if (i == 0) row[n] = EE_EDGES;
}

__global__ void scatter_k(const int* __restrict__ src, const int* __restrict__ dst,
                          int* cursor, int* __restrict__ srcp) {
    int e = blockIdx.x * blockDim.x + threadIdx.x;
    if (e < EE_EDGES) {
        int p = atomicAdd(&cursor[dst[e]], 1);
        srcp[p] = src[e];
    }
}

// ---------------- packed-f32 (FFMA2) GEMM with fused attention scores ----------------
// C[M,NCOLS] = A[M,K] @ B[K,NCOLS]; NCOLS = heads*128, blockIdx.y = head.
// Also emits el[r*heads+head] = dot(C_row_headblock, al[head]) and er likewise.
// BM=BN=128, BK=8, 256 threads, 8x8 per thread via fma.rn.f32x2.
__global__ __launch_bounds__(256) void sgemm_ffma2(const float* __restrict__ A,
                                                   const float* __restrict__ B,
                                                   float* __restrict__ C,
                                                   int M, int K, int NCOLS,
                                                   const float* __restrict__ al,
                                                   const float* __restrict__ ar,
                                                   float* __restrict__ el,
                                                   float* __restrict__ er,
                                                   int heads) {
    __shared__ float As[8][128];
    __shared__ float Bs[8][128];
    int bm = blockIdx.x, bn = blockIdx.y;
    int t = threadIdx.x;
    int tx = t & 15, ty = t >> 4;

    unsigned long long acc2[8][4];
    #pragma unroll
    for (int i = 0; i < 8; i++)
        #pragma unroll
        for (int j = 0; j < 4; j++) acc2[i][j] = 0ull;

    int aRow = t >> 1, aCol = (t & 1) * 4;
    int bRow = t >> 5, bCol = (t & 31) * 4;
    int gRow = bm * 128 + aRow;
    bool aValid = gRow < M;
    const float* Ab = A + (size_t)(aValid ? gRow : 0) * K + aCol;
    const float* Bb = B + (size_t)bRow * NCOLS + bn * 128 + bCol;

    float4 av = aValid ? *(const float4*)(Ab) : make_float4(0.f, 0.f, 0.f, 0.f);
    float4 bv = *(const float4*)(Bb);

    for (int k0 = 0; k0 < K; k0 += 8) {
        As[aCol + 0][aRow] = av.x;
        As[aCol + 1][aRow] = av.y;
        As[aCol + 2][aRow] = av.z;
        As[aCol + 3][aRow] = av.w;
        *(float4*)&Bs[bRow][bCol] = bv;
        __syncthreads();
        if (k0 + 8 < K) {
            av = aValid ? *(const float4*)(Ab + k0 + 8) : make_float4(0.f, 0.f, 0.f, 0.f);
            bv = *(const float4*)(Bb + (size_t)(k0 + 8) * NCOLS);
        }
        #pragma unroll
        for (int kk = 0; kk < 8; ++kk) {
            float4 ra0 = *(const float4*)&As[kk][ty * 8];
            float4 ra1 = *(const float4*)&As[kk][ty * 8 + 4];
            unsigned long long a2[8];
            float rav[8] = {ra0.x, ra0.y, ra0.z, ra0.w, ra1.x, ra1.y, ra1.z, ra1.w};
            #pragma unroll
            for (int i = 0; i < 8; i++)
                asm("mov.b64 %0, {%1, %2};" : "=l"(a2[i]) : "f"(rav[i]), "f"(rav[i]));
            unsigned long long b2[4];
            #pragma unroll
            for (int j = 0; j < 4; j++)
                b2[j] = *(const unsigned long long*)&Bs[kk][tx * 8 + 2 * j];
            #pragma unroll
            for (int i = 0; i < 8; i++)
                #pragma unroll
                for (int j = 0; j < 4; j++)
                    asm("fma.rn.f32x2 %0, %1, %2, %0;"
                        : "+l"(acc2[i][j]) : "l"(a2[i]), "l"(b2[j]));
        }
        __syncthreads();
    }

    // unpack
    float c[8][8];
    #pragma unroll
    for (int i = 0; i < 8; i++)
        #pragma unroll
        for (int j = 0; j < 4; j++)
            asm("mov.b64 {%0, %1}, %2;"
                : "=f"(c[i][2 * j]), "=f"(c[i][2 * j + 1]) : "l"(acc2[i][j]));

    int head = bn;
    float4 alv0 = *(const float4*)(al + head * 128 + tx * 8);
    float4 alv1 = *(const float4*)(al + head * 128 + tx * 8 + 4);
    float4 arv0 = *(const float4*)(ar + head * 128 + tx * 8);
    float4 arv1 = *(const float4*)(ar + head * 128 + tx * 8 + 4);
    float alv[8] = {alv0.x, alv0.y, alv0.z, alv0.w, alv1.x, alv1.y, alv1.z, alv1.w};
    float arv[8] = {arv0.x, arv0.y, arv0.z, arv0.w, arv1.x, arv1.y, arv1.z, arv1.w};

    #pragma unroll
    for (int i = 0; i < 8; i++) {
        int row = bm * 128 + ty * 8 + i;
        bool ok = row < M;
        if (ok) {
            float* Cp = C + (size_t)row * NCOLS + bn * 128 + tx * 8;
            *(float4*)Cp = make_float4(c[i][0], c[i][1], c[i][2], c[i][3]);
            *(float4*)(Cp + 4) = make_float4(c[i][4], c[i][5], c[i][6], c[i][7]);
        }
        // fused scores: reduce partial dots across the 16 tx lanes (within half-warp)
        float sl = 0.f, sr = 0.f;
        #pragma unroll
        for (int j = 0; j < 8; j++) { sl += c[i][j] * alv[j]; sr += c[i][j] * arv[j]; }
        #pragma unroll
        for (int o = 8; o; o >>= 1) {
            sl += __shfl_xor_sync(0xffffffffu, sl, o);
            sr += __shfl_xor_sync(0xffffffffu, sr, o);
        }
        if (ok && tx == 0) {
            el[row * heads + head] = sl;
            er[row * heads + head] = sr;
        }
    }
}

// ---------------- edge-softmax aggregation: one warp per dst node ----------------
template <int HEADS>
__global__ void agg_kernel(const float* __restrict__ hfeat,   // [N, HEADS*128]
                           const float* __restrict__ el,      // [N*HEADS]
                           const float* __restrict__ er,      // [N*HEADS]
                           const float* __restrict__ bias,    // [HEADS*128]
                           const int* __restrict__ row,
                           const int* __restrict__ srcp,
                           float* __restrict__ out) {         // [N, HEADS*128]
    int w = (blockIdx.x * blockDim.x + threadIdx.x) >> 5;
    int lane = threadIdx.x & 31;
    if (w >= NN_NODES) return;
    int d = w;
    int s0 = row[d], s1 = row[d + 1];

    float erd[HEADS];
    #pragma unroll
    for (int h = 0; h < HEADS; h++) erd[h] = er[d * HEADS + h];

    // pass 1: per-head max of leaky_relu(el[src]+er[dst]) over incoming edges
    float m[HEADS];
    #pragma unroll
    for (int h = 0; h < HEADS; h++) m[h] = -CUDART_INF_F;
    for (int i = s0 + lane; i < s1; i += 32) {
        int s = srcp[i];
        #pragma unroll
        for (int h = 0; h < HEADS; h++) {
            float e = el[s * HEADS + h] + erd[h];
            e = (e > 0.f) ? e : 0.2f * e;
            m[h] = fmaxf(m[h], e);
        }
    }
    #pragma unroll
    for (int h = 0; h < HEADS; h++)
        #pragma unroll
        for (int o = 16; o; o >>= 1)
            m[h] = fmaxf(m[h], __shfl_xor_sync(0xffffffffu, m[h], o));

    // pass 2: accumulate exp-weights and weighted feature sums
    float4 acc[HEADS];
    float den[HEADS];
    #pragma unroll
    for (int h = 0; h < HEADS; h++) {
        acc[h] = make_float4(0.f, 0.f, 0.f, 0.f);
        den[h] = 0.f;
    }
    for (int i = s0; i < s1; ++i) {
        int s = srcp[i];  // broadcast load (same address all lanes)
        #pragma unroll
        for (int h = 0; h < HEADS; h++) {
            float e = el[s * HEADS + h] + erd[h];
            e = (e > 0.f) ? e : 0.2f * e;
            float wg = __expf(e - m[h]);
            den[h] += wg;
            float4 v = *(const float4*)(hfeat + (size_t)s * (HEADS * 128) + h * 128 + lane * 4);
            acc[h].x += wg * v.x;
            acc[h].y += wg * v.y;
            acc[h].z += wg * v.z;
            acc[h].w += wg * v.w;
        }
    }
    #pragma unroll
    for (int h = 0; h < HEADS; h++) {
        float inv = 1.0f / den[h];
        float4 b4 = *(const float4*)(bias + h * 128 + lane * 4);
        float4 r;
        r.x = acc[h].x * inv + b4.x;
        r.y = acc[h].y * inv + b4.y;
        r.z = acc[h].z * inv + b4.z;
        r.w = acc[h].w * inv + b4.w;
        *(float4*)(out + (size_t)d * (HEADS * 128) + h * 128 + lane * 4) = r;
    }
}

// ---------------- launch ----------------
static inline int cdiv(int a, int b) { return (a + b - 1) / b; }

extern "C" void kernel_launch(void* const* d_in, const int* in_sizes, int n_in,
                              void* d_out, int out_size) {
    const float* feats   = (const float*)d_in[0];   // [20000,128]
    const float* W1      = (const float*)d_in[1];   // [128,384]
    const float* attn_l1 = (const float*)d_in[2];   // [3,128]
    const float* attn_r1 = (const float*)d_in[3];   // [3,128]
    const float* bias1   = (const float*)d_in[4];   // [384]
    const float* W2      = (const float*)d_in[5];   // [384,128]
    const float* attn_l2 = (const float*)d_in[6];   // [1,128]
    const float* attn_r2 = (const float*)d_in[7];   // [1,128]
    const float* bias2   = (const float*)d_in[8];   // [128]
    const int*   src     = (const int*)d_in[9];     // [320000]
    const int*   dst     = (const int*)d_in[10];    // [320000]
    float* out = (float*)d_out;                     // [20000,128]

    float *h1, *rst1, *h2, *el1, *er1, *el2, *er2;
    int *row, *cursor, *srcp, *bsums;
    cudaGetSymbolAddress((void**)&h1, g_h1);
    cudaGetSymbolAddress((void**)&rst1, g_rst1);
    cudaGetSymbolAddress((void**)&h2, g_h2);
    cudaGetSymbolAddress((void**)&el1, g_el1);
    cudaGetSymbolAddress((void**)&er1, g_er1);
    cudaGetSymbolAddress((void**)&el2, g_el2);
    cudaGetSymbolAddress((void**)&er2, g_er2);
    cudaGetSymbolAddress((void**)&row, g_row);
    cudaGetSymbolAddress((void**)&cursor, g_cursor);
    cudaGetSymbolAddress((void**)&srcp, g_srcp);
    cudaGetSymbolAddress((void**)&bsums, g_bsums);

    const int nb = cdiv(NN_NODES, 512);  // 40 scan blocks

    // CSR build (per-launch; deterministic workload)
    zero_counts_k<<<cdiv(NN_NODES + 1, 256), 256>>>(row);
    count_k<<<cdiv(EE_EDGES, 256), 256>>>(dst, row);
    scan_block_k<<<nb, 512>>>(row, bsums, NN_NODES);
    scan_add_k<<<cdiv(NN_NODES, 256), 256>>>(row, bsums, cursor, NN_NODES, nb);
    scatter_k<<<cdiv(EE_EDGES, 256), 256>>>(src, dst, cursor, srcp);

    // layer 1: GEMM + fused scores
    {
        dim3 grid(cdiv(NN_NODES, 128), 3);
        sgemm_ffma2<<<grid, 256>>>(feats, W1, h1, NN_NODES, 128, 384,
                                   attn_l1, attn_r1, el1, er1, HH1);
    }
    agg_kernel<HH1><<<cdiv(NN_NODES * 32, 256), 256>>>(h1, el1, er1, bias1, row, srcp, rst1);

    // layer 2: GEMM + fused scores
    {
        dim3 grid(cdiv(NN_NODES, 128), 1);
        sgemm_ffma2<<<grid, 256>>>(rst1, W2, h2, NN_NODES, 384, 128,
                                   attn_l2, attn_r2, el2, er2, 1);
    }
    agg_kernel<1><<<cdiv(NN_NODES * 32, 256), 256>>>(h2, el2, er2, bias2, row, srcp, out);
}

// round 4
// speedup vs baseline: 1.3361x; 1.2461x over previous
#include <cuda_runtime.h>
#include <cuda_bf16.h>
#include <math_constants.h>
#include <cstdint>

#define NN_NODES 20000
#define EE_EDGES 320000
#define FF 128
#define HH1 3

// ---------------- scratch (static device allocations) ----------------
__device__ float g_h1[NN_NODES * HH1 * FF];    // layer1 projected feats fp32 [N,384]
__device__ float g_h2[NN_NODES * FF];          // layer2 projected feats fp32 [N,128]
__device__ float g_el1[NN_NODES * HH1];
__device__ float g_er1[NN_NODES * HH1];
__device__ float g_el2[NN_NODES];
__device__ float g_er2[NN_NODES];
__device__ int   g_row[NN_NODES + 1];
__device__ int   g_cursor[NN_NODES];
__device__ int   g_srcp[EE_EDGES];
__device__ int   g_bsums[64];
// K-concatenated bf16 operands: A' = [hi, hi, lo], B' = [hi, lo, hi]
__device__ __align__(16) __nv_bfloat16 g_a1cat[NN_NODES * 3 * FF];        // [N,384]
__device__ __align__(16) __nv_bfloat16 g_a2cat[(size_t)NN_NODES * 1152]; // [N,1152]
__device__ __align__(16) __nv_bfloat16 g_b1cat[384 * 384];               // [Ncols=384, K'=384]
__device__ __align__(16) __nv_bfloat16 g_b2cat[128 * 1152];              // [Ncols=128, K'=1152]

// ---------------- helpers ----------------
__device__ __forceinline__ uint32_t smem_u32(const void* p) {
    uint32_t a;
    asm("{ .reg .u64 t; cvta.to.shared.u64 t, %1; cvt.u32.u64 %0, t; }" : "=r"(a) : "l"(p));
    return a;
}
#define LDSM_X4(r0, r1, r2, r3, addr) \
    asm volatile("ldmatrix.sync.aligned.m8n8.x4.shared.b16 {%0,%1,%2,%3}, [%4];" \
                 : "=r"(r0), "=r"(r1), "=r"(r2), "=r"(r3) : "r"(addr))

__device__ __forceinline__ void mma16816(float* d, const uint32_t* a, const uint32_t* b) {
    asm volatile(
        "mma.sync.aligned.m16n8k16.row.col.f32.bf16.bf16.f32 "
        "{%0,%1,%2,%3}, {%4,%5,%6,%7}, {%8,%9}, {%0,%1,%2,%3};"
        : "+f"(d[0]), "+f"(d[1]), "+f"(d[2]), "+f"(d[3])
        : "r"(a[0]), "r"(a[1]), "r"(a[2]), "r"(a[3]), "r"(b[0]), "r"(b[1]));
}

// ---------------- bf16 mma.sync GEMM ----------------
// C[M,NCOLS] = A[M,Kp] @ B[NCOLS,Kp]^T  (both row-major / K-major), fp32 out.
// Block 128x128 (grid.y = N chunk), 256 threads = 8 warps of 64x32 tiles.
__global__ __launch_bounds__(256) void gemm_mma(const __nv_bfloat16* __restrict__ A,
                                                const __nv_bfloat16* __restrict__ B,
                                                float* __restrict__ C,
                                                int M, int Kp, int NCOLS) {
    __shared__ __align__(16) uint8_t sA[8192];  // 128 rows x 64B (BK=32 bf16), xor-swizzled
    __shared__ __align__(16) uint8_t sB[8192];
    const int tid = threadIdx.x, lane = tid & 31, wid = tid >> 5;
    const int bm = blockIdx.x, bn = blockIdx.y;
    const int wm = (wid & 1) * 64, wn = (wid >> 1) * 32;
    const uint32_t sAb = smem_u32(sA), sBb = smem_u32(sB);

    float acc[4][4][4];
    #pragma unroll
    for (int i = 0; i < 4; i++)
        #pragma unroll
        for (int j = 0; j < 4; j++)
            #pragma unroll
            for (int q = 0; q < 4; q++) acc[i][j][q] = 0.f;

    // ldmatrix per-lane addressing pieces
    const int lrow = ((lane >> 3) & 1) * 8 + (lane & 7);  // row within 16-row group
    const int lch = lane >> 4;                            // k8-half (0/1)

    for (int k0 = 0; k0 < Kp; k0 += 32) {
        #pragma unroll
        for (int p = 0; p < 2; p++) {
            int g = tid + p * 256;
            int r = g >> 2, c = g & 3;
            uint32_t soff = r * 64 + ((c ^ ((r >> 1) & 3)) << 4);
            int gr = bm * 128 + r;
            uint4 v = make_uint4(0u, 0u, 0u, 0u);
            if (gr < M) v = *(const uint4*)(A + (size_t)gr * Kp + k0 + c * 8);
            *(uint4*)(sA + soff) = v;
            uint4 w = *(const uint4*)(B + (size_t)(bn * 128 + r) * Kp + k0 + c * 8);
            *(uint4*)(sB + soff) = w;
        }
        __syncthreads();
        #pragma unroll
        for (int ks = 0; ks < 2; ks++) {
            const int c = ks * 2 + lch;
            uint32_t af[4][4];
            #pragma unroll
            for (int mt = 0; mt < 4; mt++) {
                int r = wm + mt * 16 + lrow;
                uint32_t addr = sAb + r * 64 + ((c ^ ((r >> 1) & 3)) << 4);
                LDSM_X4(af[mt][0], af[mt][1], af[mt][2], af[mt][3], addr);
            }
            uint32_t bf[4][2];
            #pragma unroll
            for (int h = 0; h < 2; h++) {
                int r = wn + h * 16 + lrow;
                uint32_t addr = sBb + r * 64 + ((c ^ ((r >> 1) & 3)) << 4);
                uint32_t t0, t1, t2, t3;
                LDSM_X4(t0, t1, t2, t3, addr);
                bf[h * 2 + 0][0] = t0; bf[h * 2 + 0][1] = t2;
                bf[h * 2 + 1][0] = t1; bf[h * 2 + 1][1] = t3;
            }
            #pragma unroll
            for (int mt = 0; mt < 4; mt++)
                #pragma unroll
                for (int nt = 0; nt < 4; nt++)
                    mma16816(acc[mt][nt], af[mt], bf[nt]);
        }
        __syncthreads();
    }

    #pragma unroll
    for (int mt = 0; mt < 4; mt++) {
        int gr0 = bm * 128 + wm + mt * 16 + (lane >> 2);
        #pragma unroll
        for (int nt = 0; nt < 4; nt++) {
            int gc = bn * 128 + wn + nt * 8 + (lane & 3) * 2;
            if (gr0 < M)
                *(float2*)(C + (size_t)gr0 * NCOLS + gc) =
                    make_float2(acc[mt][nt][0], acc[mt][nt][1]);
            if (gr0 + 8 < M)
                *(float2*)(C + (size_t)(gr0 + 8) * NCOLS + gc) =
                    make_float2(acc[mt][nt][2], acc[mt][nt][3]);
        }
    }
}

// ---------------- prep: operand construction ----------------
__global__ void prep_a1(const float* __restrict__ feats, __nv_bfloat16* __restrict__ a1) {
    int i = blockIdx.x * blockDim.x + threadIdx.x;
    if (i < NN_NODES * FF) {
        int n = i >> 7, k = i & 127;
        float v = feats[i];
        __nv_bfloat16 h = __float2bfloat16(v);
        __nv_bfloat16 l = __float2bfloat16(v - __bfloat162float(h));
        size_t base = (size_t)n * 384 + k;
        a1[base] = h;
        a1[base + 128] = h;
        a1[base + 256] = l;
    }
}
__global__ void prep_b(const float* __restrict__ W1, const float* __restrict__ W2,
                       __nv_bfloat16* __restrict__ b1, __nv_bfloat16* __restrict__ b2) {
    int i = blockIdx.x * blockDim.x + threadIdx.x;
    const int S1 = 384 * 384;
    if (i < S1) {  // B1' [384, 384]: segs [hi, lo, hi] of W1^T
        int n = i / 384, kp = i % 384;
        int k = kp & 127;
        float v = W1[k * 384 + n];
        __nv_bfloat16 h = __float2bfloat16(v);
        __nv_bfloat16 l = __float2bfloat16(v - __bfloat162float(h));
        b1[i] = (kp < 128) ? h : ((kp < 256) ? l : h);
    } else if (i < S1 + 128 * 1152) {  // B2' [128, 1152]: segs [hi, lo, hi] of W2^T
        int j = i - S1;
        int n = j / 1152, kp = j % 1152;
        int k = kp % 384;
        float v = W2[k * 128 + n];
        __nv_bfloat16 h = __float2bfloat16(v);
        __nv_bfloat16 l = __float2bfloat16(v - __bfloat162float(h));
        b2[j] = (kp < 384) ? h : ((kp < 768) ? l : h);
    }
}

// ---------------- attention scores: one warp per (node, head) ----------------
__global__ void score_k(const float* __restrict__ h, const float* __restrict__ al,
                        const float* __restrict__ ar, float* __restrict__ el,
                        float* __restrict__ er, int heads) {
    int g = blockIdx.x * blockDim.x + threadIdx.x;
    int w = g >> 5, lane = g & 31;
    if (w >= NN_NODES * heads) return;
    int hh = w % heads;
    float4 x = ((const float4*)(h + (size_t)w * 128))[lane];
    float4 a = ((const float4*)(al + hh * 128))[lane];
    float4 b = ((const float4*)(ar + hh * 128))[lane];
    float sl = x.x * a.x + x.y * a.y + x.z * a.z + x.w * a.w;
    float sr = x.x * b.x + x.y * b.y + x.z * b.z + x.w * b.w;
    #pragma unroll
    for (int o = 16; o; o >>= 1) {
        sl += __shfl_xor_sync(0xffffffffu, sl, o);
        sr += __shfl_xor_sync(0xffffffffu, sr, o);
    }
    if (lane == 0) { el[w] = sl; er[w] = sr; }
}

// ---------------- CSR build ----------------
__global__ void zero_counts_k(int* row) {
    int i = blockIdx.x * blockDim.x + threadIdx.x;
    if (i <= NN_NODES) row[i] = 0;
}
__global__ void count_k(const int* __restrict__ dst, int* row) {
    int e = blockIdx.x * blockDim.x + threadIdx.x;
    if (e < EE_EDGES) atomicAdd(&row[dst[e]], 1);
}
__global__ void scan_block_k(int* __restrict__ row, int* __restrict__ bsums, int n) {
    __shared__ int sm[512];
    int i = blockIdx.x * 512 + threadIdx.x;
    int v = (i < n) ? row[i] : 0;
    sm[threadIdx.x] = v;
    __syncthreads();
    #pragma unroll
    for (int off = 1; off < 512; off <<= 1) {
        int t = (threadIdx.x >= off) ? sm[threadIdx.x - off] : 0;
        __syncthreads();
        sm[threadIdx.x] += t;
        __syncthreads();
    }
    int incl = sm[threadIdx.x];
    if (i < n) row[i] = incl - v;
    if (threadIdx.x == 511) bsums[blockIdx.x] = incl;
}
__global__ void scan_add_k(int* __restrict__ row, const int* __restrict__ bsums,
                           int* __restrict__ cursor, int n, int nb) {
    __shared__ int sb[65];
    int tid = threadIdx.x;
    if (tid == 0) sb[0] = 0;
    if (tid < 64) {
        int v = (tid < nb) ? bsums[tid] : 0;
        int lane = tid & 31;
        #pragma unroll
        for (int o = 1; o < 32; o <<= 1) {
            int t = __shfl_up_sync(0xffffffffu, v, o);
            if (lane >= o) v += t;
        }
        sb[tid + 1] = v;
    }
    __syncthreads();
    if (tid >= 32 && tid < 64) sb[tid + 1] += sb[32];
    __syncthreads();
    int i = blockIdx.x * blockDim.x + tid;
    if (i < n) {
        int v = row[i] + sb[i >> 9];
        row[i] = v;
        cursor[i] = v;
    }
    if (i == 0) row[n] = EE_EDGES;
}
__global__ void scatter_k(const int* __restrict__ src, const int* __restrict__ dst,
                          int* cursor, int* __restrict__ srcp) {
    int e = blockIdx.x * blockDim.x + threadIdx.x;
    if (e < EE_EDGES) {
        int p = atomicAdd(&cursor[dst[e]], 1);
        srcp[p] = src[e];
    }
}

// ---------------- edge-softmax aggregation: one warp per dst node ----------------
// BF16OUT: additionally writes the concatenated layer-2 A operand [N,1152].
template <int HEADS, bool BF16OUT>
__global__ void agg_kernel(const float* __restrict__ hfeat, const float* __restrict__ el,
                           const float* __restrict__ er, const float* __restrict__ bias,
                           const int* __restrict__ row, const int* __restrict__ srcp,
                           float* __restrict__ out, __nv_bfloat16* __restrict__ ocat) {
    int w = (blockIdx.x * blockDim.x + threadIdx.x) >> 5;
    int lane = threadIdx.x & 31;
    if (w >= NN_NODES) return;
    int d = w;
    int s0 = row[d], s1 = row[d + 1];

    float erd[HEADS];
    #pragma unroll
    for (int h = 0; h < HEADS; h++) erd[h] = er[d * HEADS + h];

    float m[HEADS];
    #pragma unroll
    for (int h = 0; h < HEADS; h++) m[h] = -CUDART_INF_F;
    for (int i = s0 + lane; i < s1; i += 32) {
        int s = srcp[i];
        #pragma unroll
        for (int h = 0; h < HEADS; h++) {
            float e = el[s * HEADS + h] + erd[h];
            e = (e > 0.f) ? e : 0.2f * e;
            m[h] = fmaxf(m[h], e);
        }
    }
    #pragma unroll
    for (int h = 0; h < HEADS; h++)
        #pragma unroll
        for (int o = 16; o; o >>= 1)
            m[h] = fmaxf(m[h], __shfl_xor_sync(0xffffffffu, m[h], o));

    float4 acc[HEADS];
    float den[HEADS];
    #pragma unroll
    for (int h = 0; h < HEADS; h++) {
        acc[h] = make_float4(0.f, 0.f, 0.f, 0.f);
        den[h] = 0.f;
    }
    for (int i = s0; i < s1; ++i) {
        int s = srcp[i];
        #pragma unroll
        for (int h = 0; h < HEADS; h++) {
            float e = el[s * HEADS + h] + erd[h];
            e = (e > 0.f) ? e : 0.2f * e;
            float wg = __expf(e - m[h]);
            den[h] += wg;
            float4 v = *(const float4*)(hfeat + (size_t)s * (HEADS * 128) + h * 128 + lane * 4);
            acc[h].x += wg * v.x;
            acc[h].y += wg * v.y;
            acc[h].z += wg * v.z;
            acc[h].w += wg * v.w;
        }
    }
    #pragma unroll
    for (int h = 0; h < HEADS; h++) {
        float inv = 1.0f / den[h];
        float4 b4 = *(const float4*)(bias + h * 128 + lane * 4);
        float r[4];
        r[0] = acc[h].x * inv + b4.x;
        r[1] = acc[h].y * inv + b4.y;
        r[2] = acc[h].z * inv + b4.z;
        r[3] = acc[h].w * inv + b4.w;
        if (BF16OUT) {
            __nv_bfloat16 hv[4], lv[4];
            #pragma unroll
            for (int q = 0; q < 4; q++) {
                hv[q] = __float2bfloat16(r[q]);
                lv[q] = __float2bfloat16(r[q] - __bfloat162float(hv[q]));
            }
            size_t base = (size_t)d * 1152 + h * 128 + lane * 4;
            *(uint2*)(ocat + base) = *(uint2*)hv;
            *(uint2*)(ocat + base + 384) = *(uint2*)hv;
            *(uint2*)(ocat + base + 768) = *(uint2*)lv;
        } else {
            size_t base = (size_t)d * (HEADS * 128) + h * 128 + lane * 4;
            *(float4*)(out + base) = make_float4(r[0], r[1], r[2], r[3]);
        }
    }
}

// ---------------- launch ----------------
static inline int cdiv(int a, int b) { return (a + b - 1) / b; }

extern "C" void kernel_launch(void* const* d_in, const int* in_sizes, int n_in,
                              void* d_out, int out_size) {
    const float* feats   = (const float*)d_in[0];
    const float* W1      = (const float*)d_in[1];
    const float* attn_l1 = (const float*)d_in[2];
    const float* attn_r1 = (const float*)d_in[3];
    const float* bias1   = (const float*)d_in[4];
    const float* W2      = (const float*)d_in[5];
    const float* attn_l2 = (const float*)d_in[6];
    const float* attn_r2 = (const float*)d_in[7];
    const float* bias2   = (const float*)d_in[8];
    const int*   src     = (const int*)d_in[9];
    const int*   dst     = (const int*)d_in[10];
    float* out = (float*)d_out;

    float *h1, *h2, *el1, *er1, *el2, *er2;
    int *row, *cursor, *srcp, *bsums;
    __nv_bfloat16 *a1cat, *a2cat, *b1cat, *b2cat;
    cudaGetSymbolAddress((void**)&h1, g_h1);
    cudaGetSymbolAddress((void**)&h2, g_h2);
    cudaGetSymbolAddress((void**)&el1, g_el1);
    cudaGetSymbolAddress((void**)&er1, g_er1);
    cudaGetSymbolAddress((void**)&el2, g_el2);
    cudaGetSymbolAddress((void**)&er2, g_er2);
    cudaGetSymbolAddress((void**)&row, g_row);
    cudaGetSymbolAddress((void**)&cursor, g_cursor);
    cudaGetSymbolAddress((void**)&srcp, g_srcp);
    cudaGetSymbolAddress((void**)&bsums, g_bsums);
    cudaGetSymbolAddress((void**)&a1cat, g_a1cat);
    cudaGetSymbolAddress((void**)&a2cat, g_a2cat);
    cudaGetSymbolAddress((void**)&b1cat, g_b1cat);
    cudaGetSymbolAddress((void**)&b2cat, g_b2cat);

    const int nb = cdiv(NN_NODES, 512);

    // CSR build
    zero_counts_k<<<cdiv(NN_NODES + 1, 256), 256>>>(row);
    count_k<<<cdiv(EE_EDGES, 256), 256>>>(dst, row);
    scan_block_k<<<nb, 512>>>(row, bsums, NN_NODES);
    scan_add_k<<<cdiv(NN_NODES, 256), 256>>>(row, bsums, cursor, NN_NODES, nb);
    scatter_k<<<cdiv(EE_EDGES, 256), 256>>>(src, dst, cursor, srcp);

    // operand prep
    prep_a1<<<cdiv(NN_NODES * FF, 256), 256>>>(feats, a1cat);
    prep_b<<<cdiv(384 * 384 + 128 * 1152, 256), 256>>>(W1, W2, b1cat, b2cat);

    const int gblocks = cdiv(NN_NODES, 128);  // 157

    // layer 1: bf16 mma GEMM (K'=384, NCOLS=384)
    {
        dim3 grid(gblocks, 3);
        gemm_mma<<<grid, 256>>>(a1cat, b1cat, h1, NN_NODES, 384, 384);
    }
    score_k<<<cdiv(NN_NODES * HH1 * 32, 256), 256>>>(h1, attn_l1, attn_r1, el1, er1, HH1);
    agg_kernel<HH1, true><<<cdiv(NN_NODES * 32, 256), 256>>>(
        h1, el1, er1, bias1, row, srcp, nullptr, a2cat);

    // layer 2: bf16 mma GEMM (K'=1152, NCOLS=128)
    {
        dim3 grid(gblocks, 1);
        gemm_mma<<<grid, 256>>>(a2cat, b2cat, h2, NN_NODES, 1152, 128);
    }
    score_k<<<cdiv(NN_NODES * 32, 256), 256>>>(h2, attn_l2, attn_r2, el2, er2, 1);
    agg_kernel<1, false><<<cdiv(NN_NODES * 32, 256), 256>>>(
        h2, el2, er2, bias2, row, srcp, out, nullptr);
}

// round 5
// speedup vs baseline: 1.5029x; 1.1248x over previous
#include <cuda_runtime.h>
#include <cuda_bf16.h>
#include <math_constants.h>
#include <cstdint>

#define NN_NODES 20000
#define EE_EDGES 320000
#define FF 128
#define HH1 3

// ---------------- scratch (static device allocations) ----------------
__device__ float g_h1[NN_NODES * HH1 * FF];    // layer1 projected feats fp32 [N,384]
__device__ float g_h2[NN_NODES * FF];          // layer2 projected feats fp32 [N,128]
__device__ float g_el1[NN_NODES * 4];          // padded stride 4
__device__ float g_er1[NN_NODES * 4];
__device__ float g_el2[NN_NODES];
__device__ float g_er2[NN_NODES];
__device__ float g_w1[3 * EE_EDGES];           // per-edge exp weights, plane-major [h][i]
__device__ float g_w2[EE_EDGES];
__device__ int   g_row[NN_NODES + 1];
__device__ int   g_cursor[NN_NODES];
__device__ int   g_srcp[EE_EDGES];             // src per CSR slot
__device__ int   g_dstp[EE_EDGES];             // dst per CSR slot
__device__ int   g_bsums[64];
// K-concatenated bf16 operands: A' = [hi, hi, lo], B' = [hi, lo, hi]
__device__ __align__(16) __nv_bfloat16 g_a1cat[NN_NODES * 3 * FF];        // [N,384]
__device__ __align__(16) __nv_bfloat16 g_a2cat[(size_t)NN_NODES * 1152]; // [N,1152]
__device__ __align__(16) __nv_bfloat16 g_b1cat[384 * 384];
__device__ __align__(16) __nv_bfloat16 g_b2cat[128 * 1152];

// ---------------- helpers ----------------
__device__ __forceinline__ uint32_t smem_u32(const void* p) {
    uint32_t a;
    asm("{ .reg .u64 t; cvta.to.shared.u64 t, %1; cvt.u32.u64 %0, t; }" : "=r"(a) : "l"(p));
    return a;
}
#define LDSM_X4(r0, r1, r2, r3, addr) \
    asm volatile("ldmatrix.sync.aligned.m8n8.x4.shared.b16 {%0,%1,%2,%3}, [%4];" \
                 : "=r"(r0), "=r"(r1), "=r"(r2), "=r"(r3) : "r"(addr))

__device__ __forceinline__ void mma16816(float* d, const uint32_t* a, const uint32_t* b) {
    asm volatile(
        "mma.sync.aligned.m16n8k16.row.col.f32.bf16.bf16.f32 "
        "{%0,%1,%2,%3}, {%4,%5,%6,%7}, {%8,%9}, {%0,%1,%2,%3};"
        : "+f"(d[0]), "+f"(d[1]), "+f"(d[2]), "+f"(d[3])
        : "r"(a[0]), "r"(a[1]), "r"(a[2]), "r"(a[3]), "r"(b[0]), "r"(b[1]));
}

// ---------------- bf16 mma.sync GEMM ----------------
__global__ __launch_bounds__(256) void gemm_mma(const __nv_bfloat16* __restrict__ A,
                                                const __nv_bfloat16* __restrict__ B,
                                                float* __restrict__ C,
                                                int M, int Kp, int NCOLS) {
    __shared__ __align__(16) uint8_t sA[8192];
    __shared__ __align__(16) uint8_t sB[8192];
    const int tid = threadIdx.x, lane = tid & 31, wid = tid >> 5;
    const int bm = blockIdx.x, bn = blockIdx.y;
    const int wm = (wid & 1) * 64, wn = (wid >> 1) * 32;
    const uint32_t sAb = smem_u32(sA), sBb = smem_u32(sB);

    float acc[4][4][4];
    #pragma unroll
    for (int i = 0; i < 4; i++)
        #pragma unroll
        for (int j = 0; j < 4; j++)
            #pragma unroll
            for (int q = 0; q < 4; q++) acc[i][j][q] = 0.f;

    const int lrow = ((lane >> 3) & 1) * 8 + (lane & 7);
    const int lch = lane >> 4;

    for (int k0 = 0; k0 < Kp; k0 += 32) {
        #pragma unroll
        for (int p = 0; p < 2; p++) {
            int g = tid + p * 256;
            int r = g >> 2, c = g & 3;
            uint32_t soff = r * 64 + ((c ^ ((r >> 1) & 3)) << 4);
            int gr = bm * 128 + r;
            uint4 v = make_uint4(0u, 0u, 0u, 0u);
            if (gr < M) v = *(const uint4*)(A + (size_t)gr * Kp + k0 + c * 8);
            *(uint4*)(sA + soff) = v;
            uint4 w = *(const uint4*)(B + (size_t)(bn * 128 + r) * Kp + k0 + c * 8);
            *(uint4*)(sB + soff) = w;
        }
        __syncthreads();
        #pragma unroll
        for (int ks = 0; ks < 2; ks++) {
            const int c = ks * 2 + lch;
            uint32_t af[4][4];
            #pragma unroll
            for (int mt = 0; mt < 4; mt++) {
                int r = wm + mt * 16 + lrow;
                uint32_t addr = sAb + r * 64 + ((c ^ ((r >> 1) & 3)) << 4);
                LDSM_X4(af[mt][0], af[mt][1], af[mt][2], af[mt][3], addr);
            }
            uint32_t bf[4][2];
            #pragma unroll
            for (int h = 0; h < 2; h++) {
                int r = wn + h * 16 + lrow;
                uint32_t addr = sBb + r * 64 + ((c ^ ((r >> 1) & 3)) << 4);
                uint32_t t0, t1, t2, t3;
                LDSM_X4(t0, t1, t2, t3, addr);
                bf[h * 2 + 0][0] = t0; bf[h * 2 + 0][1] = t2;
                bf[h * 2 + 1][0] = t1; bf[h * 2 + 1][1] = t3;
            }
            #pragma unroll
            for (int mt = 0; mt < 4; mt++)
                #pragma unroll
                for (int nt = 0; nt < 4; nt++)
                    mma16816(acc[mt][nt], af[mt], bf[nt]);
        }
        __syncthreads();
    }

    #pragma unroll
    for (int mt = 0; mt < 4; mt++) {
        int gr0 = bm * 128 + wm + mt * 16 + (lane >> 2);
        #pragma unroll
        for (int nt = 0; nt < 4; nt++) {
            int gc = bn * 128 + wn + nt * 8 + (lane & 3) * 2;
            if (gr0 < M)
                *(float2*)(C + (size_t)gr0 * NCOLS + gc) =
                    make_float2(acc[mt][nt][0], acc[mt][nt][1]);
            if (gr0 + 8 < M)
                *(float2*)(C + (size_t)(gr0 + 8) * NCOLS + gc) =
                    make_float2(acc[mt][nt][2], acc[mt][nt][3]);
        }
    }
}

// ---------------- prep: operand construction ----------------
__global__ void prep_a1(const float* __restrict__ feats, __nv_bfloat16* __restrict__ a1) {
    int i = blockIdx.x * blockDim.x + threadIdx.x;
    if (i < NN_NODES * FF) {
        int n = i >> 7, k = i & 127;
        float v = feats[i];
        __nv_bfloat16 h = __float2bfloat16(v);
        __nv_bfloat16 l = __float2bfloat16(v - __bfloat162float(h));
        size_t base = (size_t)n * 384 + k;
        a1[base] = h;
        a1[base + 128] = h;
        a1[base + 256] = l;
    }
}
__global__ void prep_b(const float* __restrict__ W1, const float* __restrict__ W2,
                       __nv_bfloat16* __restrict__ b1, __nv_bfloat16* __restrict__ b2) {
    int i = blockIdx.x * blockDim.x + threadIdx.x;
    const int S1 = 384 * 384;
    if (i < S1) {
        int n = i / 384, kp = i % 384;
        int k = kp & 127;
        float v = W1[k * 384 + n];
        __nv_bfloat16 h = __float2bfloat16(v);
        __nv_bfloat16 l = __float2bfloat16(v - __bfloat162float(h));
        b1[i] = (kp < 128) ? h : ((kp < 256) ? l : h);
    } else if (i < S1 + 128 * 1152) {
        int j = i - S1;
        int n = j / 1152, kp = j % 1152;
        int k = kp % 384;
        float v = W2[k * 128 + n];
        __nv_bfloat16 h = __float2bfloat16(v);
        __nv_bfloat16 l = __float2bfloat16(v - __bfloat162float(h));
        b2[j] = (kp < 384) ? h : ((kp < 768) ? l : h);
    }
}

// ---------------- attention scores: one warp per (node, head), stride-ST output ----------------
__global__ void score_k(const float* __restrict__ h, const float* __restrict__ al,
                        const float* __restrict__ ar, float* __restrict__ el,
                        float* __restrict__ er, int heads, int st) {
    int g = blockIdx.x * blockDim.x + threadIdx.x;
    int w = g >> 5, lane = g & 31;
    if (w >= NN_NODES * heads) return;
    int hh = w % heads, node = w / heads;
    float4 x = ((const float4*)(h + (size_t)w * 128))[lane];
    float4 a = ((const float4*)(al + hh * 128))[lane];
    float4 b = ((const float4*)(ar + hh * 128))[lane];
    float sl = x.x * a.x + x.y * a.y + x.z * a.z + x.w * a.w;
    float sr = x.x * b.x + x.y * b.y + x.z * b.z + x.w * b.w;
    #pragma unroll
    for (int o = 16; o; o >>= 1) {
        sl += __shfl_xor_sync(0xffffffffu, sl, o);
        sr += __shfl_xor_sync(0xffffffffu, sr, o);
    }
    if (lane == 0) { el[node * st + hh] = sl; er[node * st + hh] = sr; }
}

// ---------------- per-edge exp weights (no-max softmax; shift-invariant) ----------------
template <int HEADS, int ST>
__global__ void edge_w_k(const int* __restrict__ srcp, const int* __restrict__ dstp,
                         const float* __restrict__ el, const float* __restrict__ er,
                         float* __restrict__ w) {
    int i = blockIdx.x * blockDim.x + threadIdx.x;
    if (i >= EE_EDGES) return;
    int s = srcp[i], d = dstp[i];
    #pragma unroll
    for (int h = 0; h < HEADS; h++) {
        float e = el[s * ST + h] + er[d * ST + h];
        e = (e > 0.f) ? e : 0.2f * e;
        w[(size_t)h * EE_EDGES + i] = __expf(e);
    }
}

// ---------------- CSR build ----------------
__global__ void zero_counts_k(int* row) {
    int i = blockIdx.x * blockDim.x + threadIdx.x;
    if (i <= NN_NODES) row[i] = 0;
}
__global__ void count_k(const int* __restrict__ dst, int* row) {
    int e = blockIdx.x * blockDim.x + threadIdx.x;
    if (e < EE_EDGES) atomicAdd(&row[dst[e]], 1);
}
__global__ void scan_block_k(int* __restrict__ row, int* __restrict__ bsums, int n) {
    __shared__ int sm[512];
    int i = blockIdx.x * 512 + threadIdx.x;
    int v = (i < n) ? row[i] : 0;
    sm[threadIdx.x] = v;
    __syncthreads();
    #pragma unroll
    for (int off = 1; off < 512; off <<= 1) {
        int t = (threadIdx.x >= off) ? sm[threadIdx.x - off] : 0;
        __syncthreads();
        sm[threadIdx.x] += t;
        __syncthreads();
    }
    int incl = sm[threadIdx.x];
    if (i < n) row[i] = incl - v;
    if (threadIdx.x == 511) bsums[blockIdx.x] = incl;
}
__global__ void scan_add_k(int* __restrict__ row, const int* __restrict__ bsums,
                           int* __restrict__ cursor, int n, int nb) {
    __shared__ int sb[65];
    int tid = threadIdx.x;
    if (tid == 0) sb[0] = 0;
    if (tid < 64) {
        int v = (tid < nb) ? bsums[tid] : 0;
        int lane = tid & 31;
        #pragma unroll
        for (int o = 1; o < 32; o <<= 1) {
            int t = __shfl_up_sync(0xffffffffu, v, o);
            if (lane >= o) v += t;
        }
        sb[tid + 1] = v;
    }
    __syncthreads();
    if (tid >= 32 && tid < 64) sb[tid + 1] += sb[32];
    __syncthreads();
    int i = blockIdx.x * blockDim.x + tid;
    if (i < n) {
        int v = row[i] + sb[i >> 9];
        row[i] = v;
        cursor[i] = v;
    }
    if (i == 0) row[n] = EE_EDGES;
}
__global__ void scatter_k(const int* __restrict__ src, const int* __restrict__ dst,
                          int* cursor, int* __restrict__ srcp, int* __restrict__ dstp) {
    int e = blockIdx.x * blockDim.x + threadIdx.x;
    if (e < EE_EDGES) {
        int d = dst[e];
        int p = atomicAdd(&cursor[d], 1);
        srcp[p] = src[e];
        dstp[p] = d;
    }
}

// ---------------- single-pass aggregation: one warp per (dst, head) ----------------
template <int HEADS, bool BF16OUT>
__global__ void agg_k(const float* __restrict__ hfeat, const float* __restrict__ w,
                      const float* __restrict__ bias, const int* __restrict__ row,
                      const int* __restrict__ srcp, float* __restrict__ out,
                      __nv_bfloat16* __restrict__ ocat) {
    int wg = (blockIdx.x * blockDim.x + threadIdx.x) >> 5;
    int lane = threadIdx.x & 31;
    if (wg >= NN_NODES * HEADS) return;
    int d = wg / HEADS, h = wg - d * HEADS;
    int s0 = row[d], s1 = row[d + 1];
    const float* wp = w + (size_t)h * EE_EDGES;

    float4 acc = make_float4(0.f, 0.f, 0.f, 0.f);
    float den = 0.f;
    #pragma unroll 2
    for (int i = s0; i < s1; ++i) {
        int s = srcp[i];
        float wt = wp[i];
        den += wt;
        float4 v = *(const float4*)(hfeat + (size_t)s * (HEADS * 128) + h * 128 + lane * 4);
        acc.x += wt * v.x;
        acc.y += wt * v.y;
        acc.z += wt * v.z;
        acc.w += wt * v.w;
    }
    float inv = 1.0f / den;
    float4 b4 = *(const float4*)(bias + h * 128 + lane * 4);
    float r[4] = {acc.x * inv + b4.x, acc.y * inv + b4.y,
                  acc.z * inv + b4.z, acc.w * inv + b4.w};
    if (BF16OUT) {
        __nv_bfloat16 hv[4], lv[4];
        #pragma unroll
        for (int q = 0; q < 4; q++) {
            hv[q] = __float2bfloat16(r[q]);
            lv[q] = __float2bfloat16(r[q] - __bfloat162float(hv[q]));
        }
        size_t base = (size_t)d * 1152 + h * 128 + lane * 4;
        *(uint2*)(ocat + base) = *(uint2*)hv;
        *(uint2*)(ocat + base + 384) = *(uint2*)hv;
        *(uint2*)(ocat + base + 768) = *(uint2*)lv;
    } else {
        *(float4*)(out + (size_t)d * (HEADS * 128) + h * 128 + lane * 4) =
            make_float4(r[0], r[1], r[2], r[3]);
    }
}

// ---------------- launch ----------------
static inline int cdiv(int a, int b) { return (a + b - 1) / b; }

extern "C" void kernel_launch(void* const* d_in, const int* in_sizes, int n_in,
                              void* d_out, int out_size) {
    const float* feats   = (const float*)d_in[0];
    const float* W1      = (const float*)d_in[1];
    const float* attn_l1 = (const float*)d_in[2];
    const float* attn_r1 = (const float*)d_in[3];
    const float* bias1   = (const float*)d_in[4];
    const float* W2      = (const float*)d_in[5];
    const float* attn_l2 = (const float*)d_in[6];
    const float* attn_r2 = (const float*)d_in[7];
    const float* bias2   = (const float*)d_in[8];
    const int*   src     = (const int*)d_in[9];
    const int*   dst     = (const int*)d_in[10];
    float* out = (float*)d_out;

    float *h1, *h2, *el1, *er1, *el2, *er2, *w1, *w2;
    int *row, *cursor, *srcp, *dstp, *bsums;
    __nv_bfloat16 *a1cat, *a2cat, *b1cat, *b2cat;
    cudaGetSymbolAddress((void**)&h1, g_h1);
    cudaGetSymbolAddress((void**)&h2, g_h2);
    cudaGetSymbolAddress((void**)&el1, g_el1);
    cudaGetSymbolAddress((void**)&er1, g_er1);
    cudaGetSymbolAddress((void**)&el2, g_el2);
    cudaGetSymbolAddress((void**)&er2, g_er2);
    cudaGetSymbolAddress((void**)&w1, g_w1);
    cudaGetSymbolAddress((void**)&w2, g_w2);
    cudaGetSymbolAddress((void**)&row, g_row);
    cudaGetSymbolAddress((void**)&cursor, g_cursor);
    cudaGetSymbolAddress((void**)&srcp, g_srcp);
    cudaGetSymbolAddress((void**)&dstp, g_dstp);
    cudaGetSymbolAddress((void**)&bsums, g_bsums);
    cudaGetSymbolAddress((void**)&a1cat, g_a1cat);
    cudaGetSymbolAddress((void**)&a2cat, g_a2cat);
    cudaGetSymbolAddress((void**)&b1cat, g_b1cat);
    cudaGetSymbolAddress((void**)&b2cat, g_b2cat);

    // side stream + fork/join events (created once; resource init only, work unchanged)
    static cudaStream_t s2 = nullptr;
    static cudaEvent_t evFork = nullptr, evJoin = nullptr;
    if (!s2) {
        cudaStreamCreateWithFlags(&s2, cudaStreamNonBlocking);
        cudaEventCreateWithFlags(&evFork, cudaEventDisableTiming);
        cudaEventCreateWithFlags(&evJoin, cudaEventDisableTiming);
    }

    const int nb = cdiv(NN_NODES, 512);

    // fork: CSR build on side stream, overlapping prep + GEMM1 + score1
    cudaEventRecord(evFork, 0);
    cudaStreamWaitEvent(s2, evFork, 0);
    zero_counts_k<<<cdiv(NN_NODES + 1, 256), 256, 0, s2>>>(row);
    count_k<<<cdiv(EE_EDGES, 256), 256, 0, s2>>>(dst, row);
    scan_block_k<<<nb, 512, 0, s2>>>(row, bsums, NN_NODES);
    scan_add_k<<<cdiv(NN_NODES, 256), 256, 0, s2>>>(row, bsums, cursor, NN_NODES, nb);
    scatter_k<<<cdiv(EE_EDGES, 256), 256, 0, s2>>>(src, dst, cursor, srcp, dstp);
    cudaEventRecord(evJoin, s2);

    // main: operand prep + layer1 GEMM + scores
    prep_a1<<<cdiv(NN_NODES * FF, 256), 256>>>(feats, a1cat);
    prep_b<<<cdiv(384 * 384 + 128 * 1152, 256), 256>>>(W1, W2, b1cat, b2cat);
    const int gblocks = cdiv(NN_NODES, 128);
    {
        dim3 grid(gblocks, 3);
        gemm_mma<<<grid, 256>>>(a1cat, b1cat, h1, NN_NODES, 384, 384);
    }
    score_k<<<cdiv(NN_NODES * HH1 * 32, 256), 256>>>(h1, attn_l1, attn_r1, el1, er1, HH1, 4);

    // join: edge weights + aggregation need CSR
    cudaStreamWaitEvent(0, evJoin, 0);
    edge_w_k<HH1, 4><<<cdiv(EE_EDGES, 256), 256>>>(srcp, dstp, el1, er1, w1);
    agg_k<HH1, true><<<cdiv(NN_NODES * HH1 * 32, 256), 256>>>(
        h1, w1, bias1, row, srcp, nullptr, a2cat);

    // layer 2
    {
        dim3 grid(gblocks, 1);
        gemm_mma<<<grid, 256>>>(a2cat, b2cat, h2, NN_NODES, 1152, 128);
    }
    score_k<<<cdiv(NN_NODES * 32, 256), 256>>>(h2, attn_l2, attn_r2, el2, er2, 1, 1);
    edge_w_k<1, 1><<<cdiv(EE_EDGES, 256), 256>>>(srcp, dstp, el2, er2, w2);
    agg_k<1, false><<<cdiv(NN_NODES * 32, 256), 256>>>(
        h2, w2, bias2, row, srcp, out, nullptr);
}

// round 6
// speedup vs baseline: 1.7465x; 1.1621x over previous
#include <cuda_runtime.h>
#include <cuda_bf16.h>
#include <math_constants.h>
#include <cstdint>

#define NN_NODES 20000
#define EE_EDGES 320000
#define FF 128
#define HH1 3

// ---------------- scratch (static device allocations) ----------------
__device__ float g_h1[NN_NODES * HH1 * FF];    // layer1 projected feats fp32 [N,384]
__device__ float g_h2[NN_NODES * FF];          // layer2 projected feats fp32 [N,128]
__device__ float g_el1[NN_NODES * 4];          // stride 4 (3 heads + pad)
__device__ float g_er1[NN_NODES * 4];
__device__ float g_el2[NN_NODES];
__device__ float g_er2[NN_NODES];
__device__ int   g_row[NN_NODES + 1];
__device__ int   g_cursor[NN_NODES];
__device__ int   g_srcp[EE_EDGES];
__device__ int   g_bsums[64];
// A operands [M, 2K] = (hi | lo); B operands [NCOLS, 3K] = (Bhi | Blo | Bhi)
__device__ __align__(16) __nv_bfloat16 g_a1cat[NN_NODES * 256];           // [N,256]
__device__ __align__(16) __nv_bfloat16 g_a2cat[(size_t)NN_NODES * 768];  // [N,768]
__device__ __align__(16) __nv_bfloat16 g_b1cat[384 * 384];
__device__ __align__(16) __nv_bfloat16 g_b2cat[128 * 1152];

// ---------------- helpers ----------------
__device__ __forceinline__ uint32_t smem_u32(const void* p) {
    uint32_t a;
    asm("{ .reg .u64 t; cvta.to.shared.u64 t, %1; cvt.u32.u64 %0, t; }" : "=r"(a) : "l"(p));
    return a;
}
#define LDSM_X4(r0, r1, r2, r3, addr) \
    asm volatile("ldmatrix.sync.aligned.m8n8.x4.shared.b16 {%0,%1,%2,%3}, [%4];" \
                 : "=r"(r0), "=r"(r1), "=r"(r2), "=r"(r3) : "r"(addr))

__device__ __forceinline__ void mma16816(float* d, const uint32_t* a, const uint32_t* b) {
    asm volatile(
        "mma.sync.aligned.m16n8k16.row.col.f32.bf16.bf16.f32 "
        "{%0,%1,%2,%3}, {%4,%5,%6,%7}, {%8,%9}, {%0,%1,%2,%3};"
        : "+f"(d[0]), "+f"(d[1]), "+f"(d[2]), "+f"(d[3])
        : "r"(a[0]), "r"(a[1]), "r"(a[2]), "r"(a[3]), "r"(b[0]), "r"(b[1]));
}

// ---------------- bf16 mma.sync GEMM, BK=64, A hi/lo remap, fused el/er scores ----------------
// C[M,NCOLS] = A'[M,3K] @ B[NCOLS,3K]^T where A'[.,k'] = A[., k'<K ? k' : k'-K] (A stored [M,2K]).
// blockIdx.y = 128-col chunk = head; emits el[row*st+bn] = C_rowchunk . al[bn*128:], er likewise.
__global__ __launch_bounds__(256) void gemm_mma(const __nv_bfloat16* __restrict__ A,
                                                const __nv_bfloat16* __restrict__ B,
                                                float* __restrict__ C,
                                                int M, int K, int NCOLS,
                                                const float* __restrict__ al,
                                                const float* __restrict__ ar,
                                                float* __restrict__ el,
                                                float* __restrict__ er, int st) {
    __shared__ __align__(16) uint8_t sA[16384];  // 128 rows x 128B (64 bf16), xor-swizzled
    __shared__ __align__(16) uint8_t sB[16384];
    const int tid = threadIdx.x, lane = tid & 31, wid = tid >> 5;
    const int bm = blockIdx.x, bn = blockIdx.y;
    const int wm = (wid & 1) * 64, wn = (wid >> 1) * 32;
    const uint32_t sAb = smem_u32(sA), sBb = smem_u32(sB);
    const int Kp = 3 * K, Ald = 2 * K;

    float acc[4][4][4];
    #pragma unroll
    for (int i = 0; i < 4; i++)
        #pragma unroll
        for (int j = 0; j < 4; j++)
            #pragma unroll
            for (int q = 0; q < 4; q++) acc[i][j][q] = 0.f;

    const int lrow = ((lane >> 3) & 1) * 8 + (lane & 7);
    const int lch = lane >> 4;

    uint4 avr[4], bvr[4];
    // prefetch k0 = 0
    {
        #pragma unroll
        for (int p = 0; p < 4; p++) {
            int g = tid + p * 256, r = g >> 3, c = g & 7;
            int gr = bm * 128 + r;
            avr[p] = (gr < M) ? *(const uint4*)(A + (size_t)gr * Ald + c * 8)
                              : make_uint4(0u, 0u, 0u, 0u);
            bvr[p] = *(const uint4*)(B + (size_t)(bn * 128 + r) * Kp + c * 8);
        }
    }

    for (int k0 = 0; k0 < Kp; k0 += 64) {
        #pragma unroll
        for (int p = 0; p < 4; p++) {
            int g = tid + p * 256, r = g >> 3, c = g & 7;
            uint32_t soff = r * 128 + ((c ^ (r & 7)) << 4);
            *(uint4*)(sA + soff) = avr[p];
            *(uint4*)(sB + soff) = bvr[p];
        }
        __syncthreads();
        if (k0 + 64 < Kp) {
            int kn = k0 + 64;
            int abase = (kn < K) ? kn : kn - K;
            #pragma unroll
            for (int p = 0; p < 4; p++) {
                int g = tid + p * 256, r = g >> 3, c = g & 7;
                int gr = bm * 128 + r;
                avr[p] = (gr < M) ? *(const uint4*)(A + (size_t)gr * Ald + abase + c * 8)
                                  : make_uint4(0u, 0u, 0u, 0u);
                bvr[p] = *(const uint4*)(B + (size_t)(bn * 128 + r) * Kp + kn + c * 8);
            }
        }
        #pragma unroll
        for (int ks = 0; ks < 4; ks++) {
            const int c = ks * 2 + lch;
            uint32_t af[4][4];
            #pragma unroll
            for (int mt = 0; mt < 4; mt++) {
                int r = wm + mt * 16 + lrow;
                uint32_t addr = sAb + r * 128 + ((c ^ (r & 7)) << 4);
                LDSM_X4(af[mt][0], af[mt][1], af[mt][2], af[mt][3], addr);
            }
            uint32_t bf[4][2];
            #pragma unroll
            for (int h = 0; h < 2; h++) {
                int r = wn + h * 16 + lrow;
                uint32_t addr = sBb + r * 128 + ((c ^ (r & 7)) << 4);
                uint32_t t0, t1, t2, t3;
                LDSM_X4(t0, t1, t2, t3, addr);
                bf[h * 2 + 0][0] = t0; bf[h * 2 + 0][1] = t2;
                bf[h * 2 + 1][0] = t1; bf[h * 2 + 1][1] = t3;
            }
            #pragma unroll
            for (int mt = 0; mt < 4; mt++)
                #pragma unroll
                for (int nt = 0; nt < 4; nt++)
                    mma16816(acc[mt][nt], af[mt], bf[nt]);
        }
        __syncthreads();
    }

    // ---- C write + fused score partials ----
    float ps[4][4];  // [mt][{sl_row0, sr_row0, sl_row1, sr_row1}]
    #pragma unroll
    for (int mt = 0; mt < 4; mt++) {
        int gr0 = bm * 128 + wm + mt * 16 + (lane >> 2);
        float pl0 = 0.f, pr0 = 0.f, pl1 = 0.f, pr1 = 0.f;
        #pragma unroll
        for (int nt = 0; nt < 4; nt++) {
            int col = wn + nt * 8 + (lane & 3) * 2;
            int gc = bn * 128 + col;
            if (gr0 < M)
                *(float2*)(C + (size_t)gr0 * NCOLS + gc) =
                    make_float2(acc[mt][nt][0], acc[mt][nt][1]);
            if (gr0 + 8 < M)
                *(float2*)(C + (size_t)(gr0 + 8) * NCOLS + gc) =
                    make_float2(acc[mt][nt][2], acc[mt][nt][3]);
            float a0 = al[gc], a1 = al[gc + 1];
            float b0 = ar[gc], b1 = ar[gc + 1];
            pl0 += acc[mt][nt][0] * a0 + acc[mt][nt][1] * a1;
            pr0 += acc[mt][nt][0] * b0 + acc[mt][nt][1] * b1;
            pl1 += acc[mt][nt][2] * a0 + acc[mt][nt][3] * a1;
            pr1 += acc[mt][nt][2] * b0 + acc[mt][nt][3] * b1;
        }
        #pragma unroll
        for (int o = 1; o <= 2; o <<= 1) {
            pl0 += __shfl_xor_sync(0xffffffffu, pl0, o);
            pr0 += __shfl_xor_sync(0xffffffffu, pr0, o);
            pl1 += __shfl_xor_sync(0xffffffffu, pl1, o);
            pr1 += __shfl_xor_sync(0xffffffffu, pr1, o);
        }
        ps[mt][0] = pl0; ps[mt][1] = pr0; ps[mt][2] = pl1; ps[mt][3] = pr1;
    }
    __syncthreads();  // smem reuse for reduction
    float (*s_sl)[4] = (float(*)[4])sA;          // [128][4]
    float (*s_sr)[4] = (float(*)[4])(sA + 2048); // [128][4]
    int wn4 = wid >> 1;
    if ((lane & 3) == 0) {
        #pragma unroll
        for (int mt = 0; mt < 4; mt++) {
            int lr0 = wm + mt * 16 + (lane >> 2);
            s_sl[lr0][wn4] = ps[mt][0];
            s_sr[lr0][wn4] = ps[mt][1];
            s_sl[lr0 + 8][wn4] = ps[mt][2];
            s_sr[lr0 + 8][wn4] = ps[mt][3];
        }
    }
    __syncthreads();
    if (tid < 128) {
        int row = bm * 128 + tid;
        if (row < M) {
            float sl = s_sl[tid][0] + s_sl[tid][1] + s_sl[tid][2] + s_sl[tid][3];
            float sr = s_sr[tid][0] + s_sr[tid][1] + s_sr[tid][2] + s_sr[tid][3];
            el[row * st + bn] = sl;
            er[row * st + bn] = sr;
        }
    }
}

// ---------------- merged prep: A1 split + both B operands ----------------
__global__ void prep_all(const float* __restrict__ feats, const float* __restrict__ W1,
                         const float* __restrict__ W2, __nv_bfloat16* __restrict__ a1,
                         __nv_bfloat16* __restrict__ b1, __nv_bfloat16* __restrict__ b2) {
    int i = blockIdx.x * blockDim.x + threadIdx.x;
    const int SA = NN_NODES * FF;
    const int S1 = 384 * 384;
    if (i < SA) {
        int n = i >> 7, k = i & 127;
        float v = feats[i];
        __nv_bfloat16 h = __float2bfloat16(v);
        __nv_bfloat16 l = __float2bfloat16(v - __bfloat162float(h));
        size_t base = (size_t)n * 256 + k;
        a1[base] = h;
        a1[base + 128] = l;
    } else if (i < SA + S1) {
        int j = i - SA;
        int n = j / 384, kp = j % 384;
        int k = kp & 127;
        float v = W1[k * 384 + n];
        __nv_bfloat16 h = __float2bfloat16(v);
        __nv_bfloat16 l = __float2bfloat16(v - __bfloat162float(h));
        b1[j] = (kp < 128) ? h : ((kp < 256) ? l : h);
    } else if (i < SA + S1 + 128 * 1152) {
        int j = i - SA - S1;
        int n = j / 1152, kp = j % 1152;
        int k = kp % 384;
        float v = W2[k * 128 + n];
        __nv_bfloat16 h = __float2bfloat16(v);
        __nv_bfloat16 l = __float2bfloat16(v - __bfloat162float(h));
        b2[j] = (kp < 384) ? h : ((kp < 768) ? l : h);
    }
}

// ---------------- CSR build ----------------
__global__ void zero_counts_k(int* row) {
    int i = blockIdx.x * blockDim.x + threadIdx.x;
    if (i <= NN_NODES) row[i] = 0;
}
__global__ void count_k(const int* __restrict__ dst, int* row) {
    int e = blockIdx.x * blockDim.x + threadIdx.x;
    if (e < EE_EDGES) atomicAdd(&row[dst[e]], 1);
}
__global__ void scan_block_k(int* __restrict__ row, int* __restrict__ bsums, int n) {
    __shared__ int sm[512];
    int i = blockIdx.x * 512 + threadIdx.x;
    int v = (i < n) ? row[i] : 0;
    sm[threadIdx.x] = v;
    __syncthreads();
    #pragma unroll
    for (int off = 1; off < 512; off <<= 1) {
        int t = (threadIdx.x >= off) ? sm[threadIdx.x - off] : 0;
        __syncthreads();
        sm[threadIdx.x] += t;
        __syncthreads();
    }
    int incl = sm[threadIdx.x];
    if (i < n) row[i] = incl - v;
    if (threadIdx.x == 511) bsums[blockIdx.x] = incl;
}
__global__ void scan_add_k(int* __restrict__ row, const int* __restrict__ bsums,
                           int* __restrict__ cursor, int n, int nb) {
    __shared__ int sb[65];
    int tid = threadIdx.x;
    if (tid == 0) sb[0] = 0;
    if (tid < 64) {
        int v = (tid < nb) ? bsums[tid] : 0;
        int lane = tid & 31;
        #pragma unroll
        for (int o = 1; o < 32; o <<= 1) {
            int t = __shfl_up_sync(0xffffffffu, v, o);
            if (lane >= o) v += t;
        }
        sb[tid + 1] = v;
    }
    __syncthreads();
    if (tid >= 32 && tid < 64) sb[tid + 1] += sb[32];
    __syncthreads();
    int i = blockIdx.x * blockDim.x + tid;
    if (i < n) {
        int v = row[i] + sb[i >> 9];
        row[i] = v;
        cursor[i] = v;
    }
    if (i == 0) row[n] = EE_EDGES;
}
__global__ void scatter_k(const int* __restrict__ src, const int* __restrict__ dst,
                          int* cursor, int* __restrict__ srcp) {
    int e = blockIdx.x * blockDim.x + threadIdx.x;
    if (e < EE_EDGES) {
        int p = atomicAdd(&cursor[dst[e]], 1);
        srcp[p] = src[e];
    }
}

// ---------------- aggregation with inline exp-weights: one warp per (dst, head) ----------------
template <int HEADS, int ST, bool BF16OUT>
__global__ void agg_k(const float* __restrict__ hfeat, const float* __restrict__ el,
                      const float* __restrict__ er, const float* __restrict__ bias,
                      const int* __restrict__ row, const int* __restrict__ srcp,
                      float* __restrict__ out, __nv_bfloat16* __restrict__ ocat) {
    int wg = (blockIdx.x * blockDim.x + threadIdx.x) >> 5;
    int lane = threadIdx.x & 31;
    if (wg >= NN_NODES * HEADS) return;
    int d = wg / HEADS, h = wg - d * HEADS;
    int s0 = row[d], s1 = row[d + 1];
    float erd = er[d * ST + h];

    float4 acc = make_float4(0.f, 0.f, 0.f, 0.f);
    float den = 0.f;
    #pragma unroll 2
    for (int i = s0; i < s1; ++i) {
        int s = srcp[i];
        float e = el[s * ST + h] + erd;
        e = (e > 0.f) ? e : 0.2f * e;
        float wt = __expf(e);
        den += wt;
        float4 v = *(const float4*)(hfeat + (size_t)s * (HEADS * 128) + h * 128 + lane * 4);
        acc.x += wt * v.x;
        acc.y += wt * v.y;
        acc.z += wt * v.z;
        acc.w += wt * v.w;
    }
    float inv = 1.0f / den;
    float4 b4 = *(const float4*)(bias + h * 128 + lane * 4);
    float r[4] = {acc.x * inv + b4.x, acc.y * inv + b4.y,
                  acc.z * inv + b4.z, acc.w * inv + b4.w};
    if (BF16OUT) {
        __nv_bfloat16 hv[4], lv[4];
        #pragma unroll
        for (int q = 0; q < 4; q++) {
            hv[q] = __float2bfloat16(r[q]);
            lv[q] = __float2bfloat16(r[q] - __bfloat162float(hv[q]));
        }
        size_t base = (size_t)d * 768 + h * 128 + lane * 4;
        *(uint2*)(ocat + base) = *(uint2*)hv;
        *(uint2*)(ocat + base + 384) = *(uint2*)lv;
    } else {
        *(float4*)(out + (size_t)d * (HEADS * 128) + h * 128 + lane * 4) =
            make_float4(r[0], r[1], r[2], r[3]);
    }
}

// ---------------- launch ----------------
static inline int cdiv(int a, int b) { return (a + b - 1) / b; }

extern "C" void kernel_launch(void* const* d_in, const int* in_sizes, int n_in,
                              void* d_out, int out_size) {
    const float* feats   = (const float*)d_in[0];
    const float* W1      = (const float*)d_in[1];
    const float* attn_l1 = (const float*)d_in[2];
    const float* attn_r1 = (const float*)d_in[3];
    const float* bias1   = (const float*)d_in[4];
    const float* W2      = (const float*)d_in[5];
    const float* attn_l2 = (const float*)d_in[6];
    const float* attn_r2 = (const float*)d_in[7];
    const float* bias2   = (const float*)d_in[8];
    const int*   src     = (const int*)d_in[9];
    const int*   dst     = (const int*)d_in[10];
    float* out = (float*)d_out;

    float *h1, *h2, *el1, *er1, *el2, *er2;
    int *row, *cursor, *srcp, *bsums;
    __nv_bfloat16 *a1cat, *a2cat, *b1cat, *b2cat;
    cudaGetSymbolAddress((void**)&h1, g_h1);
    cudaGetSymbolAddress((void**)&h2, g_h2);
    cudaGetSymbolAddress((void**)&el1, g_el1);
    cudaGetSymbolAddress((void**)&er1, g_er1);
    cudaGetSymbolAddress((void**)&el2, g_el2);
    cudaGetSymbolAddress((void**)&er2, g_er2);
    cudaGetSymbolAddress((void**)&row, g_row);
    cudaGetSymbolAddress((void**)&cursor, g_cursor);
    cudaGetSymbolAddress((void**)&srcp, g_srcp);
    cudaGetSymbolAddress((void**)&bsums, g_bsums);
    cudaGetSymbolAddress((void**)&a1cat, g_a1cat);
    cudaGetSymbolAddress((void**)&a2cat, g_a2cat);
    cudaGetSymbolAddress((void**)&b1cat, g_b1cat);
    cudaGetSymbolAddress((void**)&b2cat, g_b2cat);

    static cudaStream_t s2 = nullptr;
    static cudaEvent_t evFork = nullptr, evJoin = nullptr;
    if (!s2) {
        cudaStreamCreateWithFlags(&s2, cudaStreamNonBlocking);
        cudaEventCreateWithFlags(&evFork, cudaEventDisableTiming);
        cudaEventCreateWithFlags(&evJoin, cudaEventDisableTiming);
    }

    const int nb = cdiv(NN_NODES, 512);

    // fork: CSR build on side stream, overlapping prep + GEMM1
    cudaEventRecord(evFork, 0);
    cudaStreamWaitEvent(s2, evFork, 0);
    zero_counts_k<<<cdiv(NN_NODES + 1, 256), 256, 0, s2>>>(row);
    count_k<<<cdiv(EE_EDGES, 256), 256, 0, s2>>>(dst, row);
    scan_block_k<<<nb, 512, 0, s2>>>(row, bsums, NN_NODES);
    scan_add_k<<<cdiv(NN_NODES, 256), 256, 0, s2>>>(row, bsums, cursor, NN_NODES, nb);
    scatter_k<<<cdiv(EE_EDGES, 256), 256, 0, s2>>>(src, dst, cursor, srcp);
    cudaEventRecord(evJoin, s2);

    // main: prep + layer1 GEMM (scores fused)
    prep_all<<<cdiv(NN_NODES * FF + 384 * 384 + 128 * 1152, 256), 256>>>(
        feats, W1, W2, a1cat, b1cat, b2cat);
    const int gblocks = cdiv(NN_NODES, 128);
    {
        dim3 grid(gblocks, 3);
        gemm_mma<<<grid, 256>>>(a1cat, b1cat, h1, NN_NODES, 128, 384,
                                attn_l1, attn_r1, el1, er1, 4);
    }

    // join: aggregation needs CSR
    cudaStreamWaitEvent(0, evJoin, 0);
    agg_k<HH1, 4, true><<<cdiv(NN_NODES * HH1 * 32, 256), 256>>>(
        h1, el1, er1, bias1, row, srcp, nullptr, a2cat);

    // layer 2
    {
        dim3 grid(gblocks, 1);
        gemm_mma<<<grid, 256>>>(a2cat, b2cat, h2, NN_NODES, 384, 128,
                                attn_l2, attn_r2, el2, er2, 1);
    }
    agg_k<1, 1, false><<<cdiv(NN_NODES * 32, 256), 256>>>(
        h2, el2, er2, bias2, row, srcp, out, nullptr);
}